// round 1
// baseline (speedup 1.0000x reference)
#include <cuda_runtime.h>

#define IMG_H 1536
#define IMG_W 1536
#define NK 8
#define PW 7
#define NR 28      // CLIP_MAX+1 rows of F ever used
#define CLIPM 27

// Scratch (device globals only — no allocation allowed)
__device__ float g_F[NK * NR * IMG_W];   // thresholded F[k][row][j]
__device__ float g_partial[IMG_H];       // per-i row maxima

// ---------------------------------------------------------------------------
// Kernel A: F[k,row,j] = 1 - (1/49) * sum_{a,b} |P[k,a,b] - pad[a+row, b+j]|
// pad[r,c] = img[r-7, c-7] if in-bounds else 0. Only rows 0..27 needed.
// Threshold thr[k] = F_raw[k,0,0] = 1 - sum|P|/49 (all pad values are 0 there),
// computed in the SAME a-major/b-minor order so F[k,0,0] == thr bitwise -> 0.
// ---------------------------------------------------------------------------
__global__ void geneo1_kernel(const float* __restrict__ x,
                              const float* __restrict__ patterns) {
    const int k   = blockIdx.x / NR;
    const int row = blockIdx.x % NR;
    __shared__ float sp[PW * PW];
    __shared__ float sthr;
    const int tid = threadIdx.x;

    if (tid < PW * PW) sp[tid] = patterns[k * PW * PW + tid];
    __syncthreads();
    if (tid == 0) {
        float s = 0.0f;
        #pragma unroll
        for (int a = 0; a < PW; a++)
            #pragma unroll
            for (int b = 0; b < PW; b++)
                s += fabsf(sp[a * PW + b]);
        sthr = 1.0f - s * (1.0f / 49.0f);
    }
    __syncthreads();
    const float thr = sthr;

    for (int j = tid; j < IMG_W; j += blockDim.x) {
        float acc = 0.0f;
        #pragma unroll
        for (int a = 0; a < PW; a++) {
            const int r = a + row - PW;          // in [-7, 26]: only lower bound can fail
            #pragma unroll
            for (int b = 0; b < PW; b++) {
                const int c = b + j - PW;        // in [-7, 1534]: only lower bound can fail
                float v = (r >= 0 && c >= 0) ? x[r * IMG_W + c] : 0.0f;
                acc += fabsf(sp[a * PW + b] - v);
            }
        }
        float f = 1.0f - acc * (1.0f / 49.0f);
        g_F[(k * NR + row) * IMG_W + j] = (f > thr) ? f : 0.0f;
    }
}

// ---------------------------------------------------------------------------
// Kernel B: for output row i, Tk[i,j] = sum over 32 (k,corner) of w * F[k,r,j]
// where r = clip(clip(i - (s_y+dy), 0, 27) - (s_x+dx), 0, 27) is uniform per i.
// Track running max over j; write per-i max.
// ---------------------------------------------------------------------------
__global__ void geneo3_kernel(const float* __restrict__ vectors) {
    const int i   = blockIdx.x;
    const int tid = threadIdx.x;
    __shared__ int   sbase[32];
    __shared__ float sw[32];

    if (tid < 32) {
        const int k = tid >> 2;
        const int c = tid & 3;
        const float v0 = vectors[2 * k + 0];
        const float v1 = vectors[2 * k + 1];
        const float fx = floorf(v0);
        const float fy = floorf(v1);
        const int   sx = (int)fx;
        const int   sy = (int)fy;
        const float px = fx - v0;   // in (-1, 0]
        const float py = fy - v1;
        const int dx = c >> 1;      // corner order matches reference list
        const int dy = c & 1;
        const float wx = dx ? (1.0f - px) : px;
        const float wy = dy ? (1.0f - py) : py;
        int t1 = i - (sy + dy);
        t1 = min(max(t1, 0), CLIPM);
        int r = t1 - (sx + dx);
        r = min(max(r, 0), CLIPM);
        sbase[tid] = (k * NR + r) * IMG_W;
        sw[tid]    = wx * wy;
    }
    __syncthreads();

    // Hoist the 32 (base, weight) pairs to registers (loop-invariant).
    int   base[32];
    float wgt[32];
    #pragma unroll
    for (int t = 0; t < 32; t++) { base[t] = sbase[t]; wgt[t] = sw[t]; }

    float m = -1e30f;
    for (int j = tid; j < IMG_W; j += blockDim.x) {
        float acc = 0.0f;
        #pragma unroll
        for (int t = 0; t < 32; t++)
            acc = fmaf(wgt[t], __ldg(&g_F[base[t] + j]), acc);
        m = fmaxf(m, acc);
    }

    // Block max-reduce
    #pragma unroll
    for (int o = 16; o > 0; o >>= 1)
        m = fmaxf(m, __shfl_xor_sync(0xffffffffu, m, o));
    __shared__ float smax[8];
    if ((tid & 31) == 0) smax[tid >> 5] = m;
    __syncthreads();
    if (tid == 0) {
        float mm = smax[0];
        for (int w = 1; w < (int)(blockDim.x >> 5); w++) mm = fmaxf(mm, smax[w]);
        g_partial[i] = mm;
    }
}

// ---------------------------------------------------------------------------
// Kernel C: reduce 1536 partial maxima, apply the /7 from _geneo3.
// ---------------------------------------------------------------------------
__global__ void reduce_kernel(float* __restrict__ out) {
    const int tid = threadIdx.x;
    float m = -1e30f;
    for (int i = tid; i < IMG_H; i += blockDim.x)
        m = fmaxf(m, g_partial[i]);
    #pragma unroll
    for (int o = 16; o > 0; o >>= 1)
        m = fmaxf(m, __shfl_xor_sync(0xffffffffu, m, o));
    __shared__ float s[16];
    if ((tid & 31) == 0) s[tid >> 5] = m;
    __syncthreads();
    if (tid == 0) {
        float mm = s[0];
        for (int w = 1; w < (int)(blockDim.x >> 5); w++) mm = fmaxf(mm, s[w]);
        out[0] = mm * (1.0f / 7.0f);
    }
}

extern "C" void kernel_launch(void* const* d_in, const int* in_sizes, int n_in,
                              void* d_out, int out_size) {
    const float* x        = (const float*)d_in[0];
    const float* patterns = (const float*)d_in[1];
    const float* vectors  = (const float*)d_in[2];
    float* out = (float*)d_out;

    geneo1_kernel<<<NK * NR, 256>>>(x, patterns);
    geneo3_kernel<<<IMG_H, 256>>>(vectors);
    reduce_kernel<<<1, 512>>>(out);
}

// round 2
// speedup vs baseline: 2.3310x; 2.3310x over previous
#include <cuda_runtime.h>

#define IMG_H 1536
#define IMG_W 1536
#define NK 8
#define PW 7
#define NR 28      // CLIP_MAX+1 rows of F ever used
#define CLIPM 27
#define JT 6                      // j tiles of 256 in geneo1
#define NBLK1 (NK * NR * JT)      // 1344 compute blocks; block NBLK1 = setup
#define MAXI 256                  // >= 1 + 8*28 = 225 distinct row classes

// Scratch (device globals only — no allocation allowed)
__device__ __align__(16) float g_F[NK * NR * IMG_W]; // thresholded F[k][row][j]
__device__ float g_partial[MAXI];                    // per-class row maxima
__device__ int   g_ilist[MAXI];                      // representative i per class
__device__ int   g_icount;

// ---------------------------------------------------------------------------
// Kernel A: F[k,row,j] = 1 - (1/49) * sum_{a,b} |P[k,a,b] - pad[a+row, b+j]|
// One j per thread. Block NBLK1 instead builds the distinct-row-class list
// for geneo3: the gather vector r_t(i) changes only at i in [sy_k+1, sy_k+28].
// ---------------------------------------------------------------------------
__global__ void geneo1_kernel(const float* __restrict__ x,
                              const float* __restrict__ patterns,
                              const float* __restrict__ vectors) {
    const int tid = threadIdx.x;

    if (blockIdx.x == NBLK1) {
        // ---- setup: flag candidate i's, ordered warp-ballot compaction ----
        __shared__ unsigned char flags[IMG_W];
        for (int i = tid; i < IMG_W; i += blockDim.x) flags[i] = 0;
        __syncthreads();
        if (tid == 0) flags[0] = 1;
        if (tid < NK * NR) {
            const int k = tid / NR, off = tid % NR;
            const int sy = (int)floorf(vectors[2 * k + 1]);
            const int i = sy + 1 + off;
            if (i >= 1 && i < IMG_W) flags[i] = 1;
        }
        __syncthreads();
        if (tid < 32) {
            int base = 0;
            for (int ch = 0; ch < IMG_W / 32; ch++) {
                const int f = flags[ch * 32 + tid];
                const unsigned m = __ballot_sync(0xffffffffu, f);
                if (f) g_ilist[base + __popc(m & ((1u << tid) - 1u))] = ch * 32 + tid;
                base += __popc(m);
            }
            if (tid == 0) g_icount = base;
        }
        return;
    }

    const int k   = blockIdx.x / (NR * JT);
    const int rem = blockIdx.x % (NR * JT);
    const int row = rem / JT;
    const int j   = (rem % JT) * 256 + tid;

    __shared__ float sp[PW * PW];
    __shared__ float sthr;
    if (tid < PW * PW) sp[tid] = patterns[k * PW * PW + tid];
    __syncthreads();
    if (tid == 0) {
        float s = 0.0f;
        #pragma unroll
        for (int a = 0; a < PW; a++)
            #pragma unroll
            for (int b = 0; b < PW; b++)
                s += fabsf(sp[a * PW + b]);
        sthr = 1.0f - s * (1.0f / 49.0f);
    }
    __syncthreads();
    const float thr = sthr;

    float acc = 0.0f;
    #pragma unroll
    for (int a = 0; a < PW; a++) {
        const int r = a + row - PW;              // [-7, 26]
        #pragma unroll
        for (int b = 0; b < PW; b++) {
            const int c = b + j - PW;            // [-7, 1534]
            float v = (r >= 0 && c >= 0) ? __ldg(&x[r * IMG_W + c]) : 0.0f;
            acc += fabsf(sp[a * PW + b] - v);
        }
    }
    float f = 1.0f - acc * (1.0f / 49.0f);
    g_F[(k * NR + row) * IMG_W + j] = (f > thr) ? f : 0.0f;
}

// ---------------------------------------------------------------------------
// Kernel B: one block per distinct row-class. 384 threads, float4 over j.
// Tk[i,j] = sum_t w_t * F[base_t + j]; write row max.
// ---------------------------------------------------------------------------
__global__ void geneo3_kernel(const float* __restrict__ vectors) {
    const int b   = blockIdx.x;
    const int tid = threadIdx.x;
    __shared__ int   scount, si;
    __shared__ int   sbase[32];
    __shared__ float sw[32];

    if (tid == 0) {
        scount = g_icount;
        si = (b < g_icount) ? g_ilist[b] : 0;
    }
    __syncthreads();
    if (b >= scount) {
        if (tid == 0) g_partial[b] = -1e30f;
        return;
    }
    const int i = si;

    if (tid < 32) {
        const int k = tid >> 2;
        const int c = tid & 3;
        const float v0 = vectors[2 * k + 0];
        const float v1 = vectors[2 * k + 1];
        const float fx = floorf(v0);
        const float fy = floorf(v1);
        const int   sx = (int)fx;
        const int   sy = (int)fy;
        const float px = fx - v0;
        const float py = fy - v1;
        const int dx = c >> 1;       // corner order matches reference
        const int dy = c & 1;
        const float wx = dx ? (1.0f - px) : px;
        const float wy = dy ? (1.0f - py) : py;
        int t1 = i - (sy + dy);
        t1 = min(max(t1, 0), CLIPM);
        int r = t1 - (sx + dx);
        r = min(max(r, 0), CLIPM);
        sbase[tid] = (k * NR + r) * IMG_W;
        sw[tid]    = wx * wy;
    }
    __syncthreads();

    int   base[32];
    float wgt[32];
    #pragma unroll
    for (int t = 0; t < 32; t++) { base[t] = sbase[t]; wgt[t] = sw[t]; }

    // 384 threads * float4 = 1536 columns, exactly one pass
    float4 acc = make_float4(0.f, 0.f, 0.f, 0.f);
    #pragma unroll
    for (int t = 0; t < 32; t++) {
        const float4 v = *(const float4*)&g_F[base[t] + 4 * tid];
        acc.x = fmaf(wgt[t], v.x, acc.x);
        acc.y = fmaf(wgt[t], v.y, acc.y);
        acc.z = fmaf(wgt[t], v.z, acc.z);
        acc.w = fmaf(wgt[t], v.w, acc.w);
    }
    float m = fmaxf(fmaxf(acc.x, acc.y), fmaxf(acc.z, acc.w));

    #pragma unroll
    for (int o = 16; o > 0; o >>= 1)
        m = fmaxf(m, __shfl_xor_sync(0xffffffffu, m, o));
    __shared__ float smax[12];
    if ((tid & 31) == 0) smax[tid >> 5] = m;
    __syncthreads();
    if (tid == 0) {
        float mm = smax[0];
        #pragma unroll
        for (int w = 1; w < 12; w++) mm = fmaxf(mm, smax[w]);
        g_partial[b] = mm;
    }
}

// ---------------------------------------------------------------------------
// Kernel C: reduce class maxima, apply the /7 from _geneo3.
// ---------------------------------------------------------------------------
__global__ void reduce_kernel(float* __restrict__ out) {
    const int tid = threadIdx.x;
    float m = g_partial[tid];                       // blockDim == MAXI
    #pragma unroll
    for (int o = 16; o > 0; o >>= 1)
        m = fmaxf(m, __shfl_xor_sync(0xffffffffu, m, o));
    __shared__ float s[MAXI / 32];
    if ((tid & 31) == 0) s[tid >> 5] = m;
    __syncthreads();
    if (tid == 0) {
        float mm = s[0];
        #pragma unroll
        for (int w = 1; w < MAXI / 32; w++) mm = fmaxf(mm, s[w]);
        out[0] = mm * (1.0f / 7.0f);
    }
}

extern "C" void kernel_launch(void* const* d_in, const int* in_sizes, int n_in,
                              void* d_out, int out_size) {
    const float* x        = (const float*)d_in[0];
    const float* patterns = (const float*)d_in[1];
    const float* vectors  = (const float*)d_in[2];
    float* out = (float*)d_out;

    geneo1_kernel<<<NBLK1 + 1, 256>>>(x, patterns, vectors);
    geneo3_kernel<<<MAXI, 384>>>(vectors);
    reduce_kernel<<<1, MAXI>>>(out);
}

// round 4
// speedup vs baseline: 2.8496x; 1.2225x over previous
#include <cuda_runtime.h>

#define IMG_H 1536
#define IMG_W 1536
#define NK 8
#define PW 7
#define NR 28      // CLIP_MAX+1 rows of F ever used
#define CLIPM 27

#define BS1 128
#define NCH 4                     // row chunks of 7
#define JB (IMG_W / BS1)          // 12 j-blocks
#define NBLK1 (NK * NCH * JB)     // 384 compute blocks; block NBLK1 = setup
#define NBLK3 225                 // max distinct row classes: 1 + 8*28

// Scratch (device globals only — no allocation allowed)
__device__ __align__(16) float g_F[NK * NR * IMG_W]; // thresholded F[k][row][j]
__device__ int      g_ilist[NBLK3];                  // representative i per class
__device__ int      g_icount;
__device__ unsigned g_enc;                           // encoded running max
__device__ unsigned g_done;                          // completed geneo3 blocks

// Monotone float <-> uint encoding for atomicMax over signed floats.
__device__ __forceinline__ unsigned enc_f(float f) {
    int b = __float_as_int(f);
    return (b >= 0) ? ((unsigned)b | 0x80000000u) : ~(unsigned)b;
}
__device__ __forceinline__ float dec_f(unsigned u) {
    int b = (u & 0x80000000u) ? (int)(u ^ 0x80000000u) : ~(int)u;
    return __int_as_float(b);
}

// ---------------------------------------------------------------------------
// Kernel A: F[k,row,j] = 1 - (1/49) * sum_{a,b} |P[k,a,b] - pad[a+row, b+j]|
// Thread = (k, j); walks 7 output rows with a 7x7 register rolling window.
// Summation order is EXACTLY the reference's (a-major, b-minor, single chain)
// so F[k,0,0] == thr bitwise and no threshold flips are possible.
// Block NBLK1 = setup: builds distinct-row-class list, resets atomics.
// ---------------------------------------------------------------------------
__global__ void __launch_bounds__(BS1) geneo1_kernel(
        const float* __restrict__ x,
        const float* __restrict__ patterns,
        const float* __restrict__ vectors) {
    const int tid = threadIdx.x;

    if (blockIdx.x == NBLK1) {
        // ---- setup: flag candidate i's, ordered warp-ballot compaction ----
        __shared__ unsigned char flags[IMG_W];
        for (int i = tid; i < IMG_W; i += BS1) flags[i] = 0;
        __syncthreads();
        if (tid == 0) { flags[0] = 1; g_enc = 0u; g_done = 0u; }
        if (tid < NK * NR) {
            const int k = tid / NR, off = tid % NR;
            const int sy = (int)floorf(vectors[2 * k + 1]);
            const int i = sy + 1 + off;
            if (i >= 1 && i < IMG_W) flags[i] = 1;
        }
        __syncthreads();
        if (tid < 32) {
            int base = 0;
            for (int ch = 0; ch < IMG_W / 32; ch++) {
                const int f = flags[ch * 32 + tid];
                const unsigned m = __ballot_sync(0xffffffffu, f);
                if (f) g_ilist[base + __popc(m & ((1u << tid) - 1u))] = ch * 32 + tid;
                base += __popc(m);
            }
            if (tid == 0) g_icount = base;
        }
        return;
    }

    const int k   = blockIdx.x / (NCH * JB);
    const int rem = blockIdx.x % (NCH * JB);
    const int r0  = (rem / JB) * 7;               // first output row of chunk
    const int j   = (rem % JB) * BS1 + tid;

    // Pattern in registers.
    float p[PW * PW];
    #pragma unroll
    for (int t = 0; t < PW * PW; t++) p[t] = __ldg(&patterns[k * PW * PW + t]);

    // thr = F_raw(0,0): window all zeros there; same sequential order.
    float s = 0.0f;
    #pragma unroll
    for (int t = 0; t < PW * PW; t++) s += fabsf(p[t]);
    const float thr = 1.0f - s * (1.0f / 49.0f);

    // Initial window: x rows r0-7 .. r0-1, cols j-7 .. j-1 (j-7+b).
    float win[PW][PW];
    #pragma unroll
    for (int a = 0; a < PW; a++) {
        const int r = r0 - PW + a;
        #pragma unroll
        for (int b = 0; b < PW; b++) {
            const int c = j - PW + b;
            win[a][b] = (r >= 0 && c >= 0) ? __ldg(&x[r * IMG_W + c]) : 0.0f;
        }
    }

    #pragma unroll
    for (int step = 0; step < PW; step++) {
        const int row = r0 + step;
        float acc = 0.0f;
        #pragma unroll
        for (int a = 0; a < PW; a++)
            #pragma unroll
            for (int b = 0; b < PW; b++)
                acc += fabsf(p[a * PW + b] - win[a][b]);
        const float f = 1.0f - acc * (1.0f / 49.0f);
        g_F[(k * NR + row) * IMG_W + j] = (f > thr) ? f : 0.0f;

        if (step < PW - 1) {
            #pragma unroll
            for (int a = 0; a < PW - 1; a++)
                #pragma unroll
                for (int b = 0; b < PW; b++)
                    win[a][b] = win[a + 1][b];
            #pragma unroll
            for (int b = 0; b < PW; b++) {
                const int c = j - PW + b;           // row 'row' is always >= 0
                win[PW - 1][b] = (c >= 0) ? __ldg(&x[row * IMG_W + c]) : 0.0f;
            }
        }
    }
}

// ---------------------------------------------------------------------------
// Kernel B: one block per distinct row-class; float4 over j; fused global max
// via encoded atomicMax; last-arriving block writes d_out[0] = max/7.
// ---------------------------------------------------------------------------
__global__ void __launch_bounds__(384) geneo3_kernel(
        const float* __restrict__ vectors, float* __restrict__ out) {
    const int b   = blockIdx.x;
    const int tid = threadIdx.x;
    __shared__ int   scount, si;
    __shared__ int   sbase[32];
    __shared__ float sw[32];
    __shared__ float smax[12];

    if (tid == 0) {
        scount = g_icount;
        si = (b < g_icount) ? g_ilist[b] : 0;
    }
    __syncthreads();
    const bool active = (b < scount);
    float m = -3.0e38f;

    if (active) {
        const int i = si;
        if (tid < 32) {
            const int kk = tid >> 2;
            const int c  = tid & 3;
            const float v0 = vectors[2 * kk + 0];
            const float v1 = vectors[2 * kk + 1];
            const float fx = floorf(v0);
            const float fy = floorf(v1);
            const int   sx = (int)fx;
            const int   sy = (int)fy;
            const float px = fx - v0;
            const float py = fy - v1;
            const int dx = c >> 1;       // corner order matches reference
            const int dy = c & 1;
            const float wx = dx ? (1.0f - px) : px;
            const float wy = dy ? (1.0f - py) : py;
            int t1 = i - (sy + dy);
            t1 = min(max(t1, 0), CLIPM);
            int r = t1 - (sx + dx);
            r = min(max(r, 0), CLIPM);
            sbase[tid] = (kk * NR + r) * IMG_W;
            sw[tid]    = wx * wy;
        }
        __syncthreads();

        int   base[32];
        float wgt[32];
        #pragma unroll
        for (int t = 0; t < 32; t++) { base[t] = sbase[t]; wgt[t] = sw[t]; }

        // 384 threads * float4 = 1536 columns, exactly one pass.
        float4 acc = make_float4(0.f, 0.f, 0.f, 0.f);
        #pragma unroll
        for (int t = 0; t < 32; t++) {
            const float4 v = *(const float4*)&g_F[base[t] + 4 * tid];
            acc.x = fmaf(wgt[t], v.x, acc.x);
            acc.y = fmaf(wgt[t], v.y, acc.y);
            acc.z = fmaf(wgt[t], v.z, acc.z);
            acc.w = fmaf(wgt[t], v.w, acc.w);
        }
        m = fmaxf(fmaxf(acc.x, acc.y), fmaxf(acc.z, acc.w));

        #pragma unroll
        for (int o = 16; o > 0; o >>= 1)
            m = fmaxf(m, __shfl_xor_sync(0xffffffffu, m, o));
        if ((tid & 31) == 0) smax[tid >> 5] = m;
        __syncthreads();
        if (tid == 0) {
            #pragma unroll
            for (int w = 1; w < 12; w++) m = fmaxf(m, smax[w]);
        }
    }

    if (tid == 0) {
        if (active) atomicMax(&g_enc, enc_f(m));
        __threadfence();
        const unsigned old = atomicAdd(&g_done, 1u);
        if (old == (unsigned)(NBLK3 - 1)) {
            const unsigned u = atomicOr(&g_enc, 0u);   // coherent read
            out[0] = dec_f(u) * (1.0f / 7.0f);
        }
    }
}

extern "C" void kernel_launch(void* const* d_in, const int* in_sizes, int n_in,
                              void* d_out, int out_size) {
    const float* x        = (const float*)d_in[0];
    const float* patterns = (const float*)d_in[1];
    const float* vectors  = (const float*)d_in[2];
    float* out = (float*)d_out;

    geneo1_kernel<<<NBLK1 + 1, BS1>>>(x, patterns, vectors);
    geneo3_kernel<<<NBLK3, 384>>>(vectors, out);
}

// round 5
// speedup vs baseline: 2.9889x; 1.0489x over previous
#include <cuda_runtime.h>

#define IMG_H 1536
#define IMG_W 1536
#define NK 8
#define PW 7
#define NR 28      // CLIP_MAX+1 rows of F ever used
#define CLIPM 27

#define BS1 128
#define NCH 4                     // row chunks of 7
#define JB (IMG_W / BS1)          // 12 j-blocks
#define NBLK1 (NK * NCH * JB)     // 384 compute blocks; block NBLK1 = setup
#define NCLS 225                  // max distinct row classes: 1 + 8*28
#define NBLK3 (NCLS * 2)          // class x j-half

// Scratch (device globals only — no allocation allowed)
__device__ __align__(16) float g_F[NK * NR * IMG_W]; // thresholded F[k][row][j]
__device__ int      g_ilist[NCLS];                   // representative i per class
__device__ int      g_icount;
__device__ unsigned g_enc;                           // encoded running max
__device__ unsigned g_done;                          // completed geneo3 blocks

// Monotone float <-> uint encoding for atomicMax over signed floats.
__device__ __forceinline__ unsigned enc_f(float f) {
    int b = __float_as_int(f);
    return (b >= 0) ? ((unsigned)b | 0x80000000u) : ~(unsigned)b;
}
__device__ __forceinline__ float dec_f(unsigned u) {
    int b = (u & 0x80000000u) ? (int)(u ^ 0x80000000u) : ~(int)u;
    return __int_as_float(b);
}

// ---------------------------------------------------------------------------
// Kernel A: F[k,row,j] = 1 - (1/49) * sum_{a,b} |P[k,a,b] - pad[a+row, b+j]|
// Thread = (k, j); walks 7 output rows with a 7x7 register rolling window.
// Summation order is EXACTLY the reference's (a-major, b-minor, single chain)
// so F[k,0,0] == thr bitwise and no threshold flips are possible.
// Block NBLK1 = setup: builds distinct-row-class list, resets atomics.
// ---------------------------------------------------------------------------
__global__ void __launch_bounds__(BS1) geneo1_kernel(
        const float* __restrict__ x,
        const float* __restrict__ patterns,
        const float* __restrict__ vectors) {
    const int tid = threadIdx.x;

    if (blockIdx.x == NBLK1) {
        // ---- setup: flag candidate i's, ordered warp-ballot compaction ----
        __shared__ unsigned char flags[IMG_W];
        for (int i = tid; i < IMG_W; i += BS1) flags[i] = 0;
        __syncthreads();
        if (tid == 0) { flags[0] = 1; g_enc = 0u; g_done = 0u; }
        if (tid < NK * NR) {
            const int k = tid / NR, off = tid % NR;
            const int sy = (int)floorf(vectors[2 * k + 1]);
            const int i = sy + 1 + off;
            if (i >= 1 && i < IMG_W) flags[i] = 1;
        }
        __syncthreads();
        if (tid < 32) {
            int base = 0;
            for (int ch = 0; ch < IMG_W / 32; ch++) {
                const int f = flags[ch * 32 + tid];
                const unsigned m = __ballot_sync(0xffffffffu, f);
                if (f) g_ilist[base + __popc(m & ((1u << tid) - 1u))] = ch * 32 + tid;
                base += __popc(m);
            }
            if (tid == 0) g_icount = base;
        }
        return;
    }

    const int k   = blockIdx.x / (NCH * JB);
    const int rem = blockIdx.x % (NCH * JB);
    const int r0  = (rem / JB) * 7;               // first output row of chunk
    const int j   = (rem % JB) * BS1 + tid;

    // Pattern in registers.
    float p[PW * PW];
    #pragma unroll
    for (int t = 0; t < PW * PW; t++) p[t] = __ldg(&patterns[k * PW * PW + t]);

    // thr = F_raw(0,0): window all zeros there; same sequential order.
    float s = 0.0f;
    #pragma unroll
    for (int t = 0; t < PW * PW; t++) s += fabsf(p[t]);
    const float thr = 1.0f - s * (1.0f / 49.0f);

    // Initial window: x rows r0-7 .. r0-1, cols j-7 .. j-1 (j-7+b).
    float win[PW][PW];
    #pragma unroll
    for (int a = 0; a < PW; a++) {
        const int r = r0 - PW + a;
        #pragma unroll
        for (int b = 0; b < PW; b++) {
            const int c = j - PW + b;
            win[a][b] = (r >= 0 && c >= 0) ? __ldg(&x[r * IMG_W + c]) : 0.0f;
        }
    }

    #pragma unroll
    for (int step = 0; step < PW; step++) {
        const int row = r0 + step;
        float acc = 0.0f;
        #pragma unroll
        for (int a = 0; a < PW; a++)
            #pragma unroll
            for (int b = 0; b < PW; b++)
                acc += fabsf(p[a * PW + b] - win[a][b]);
        const float f = 1.0f - acc * (1.0f / 49.0f);
        g_F[(k * NR + row) * IMG_W + j] = (f > thr) ? f : 0.0f;

        if (step < PW - 1) {
            #pragma unroll
            for (int a = 0; a < PW - 1; a++)
                #pragma unroll
                for (int b = 0; b < PW; b++)
                    win[a][b] = win[a + 1][b];
            #pragma unroll
            for (int b = 0; b < PW; b++) {
                const int c = j - PW + b;           // row 'row' is always >= 0
                win[PW - 1][b] = (c >= 0) ? __ldg(&x[row * IMG_W + c]) : 0.0f;
            }
        }
    }
}

// ---------------------------------------------------------------------------
// Kernel B: block = (class, j-half). Warp 0 builds the tap list and merges
// duplicate gather rows (__match_any_sync on base; weights sum). Main loop:
// ntap iterations of smem (base,w) + float2 LDG + 2 FMA. Fused global max.
// ---------------------------------------------------------------------------
__global__ void __launch_bounds__(384) geneo3_kernel(
        const float* __restrict__ vectors, float* __restrict__ out) {
    const int cls  = blockIdx.x >> 1;
    const int half = blockIdx.x & 1;
    const int tid  = threadIdx.x;
    __shared__ int   scount, si, sntap;
    __shared__ int   sbase[32];
    __shared__ float sw[32];
    __shared__ float smax[12];

    if (tid == 0) {
        scount = g_icount;
        si = (cls < g_icount) ? g_ilist[cls] : 0;
    }
    __syncthreads();
    const bool active = (cls < scount);
    float m = -3.0e38f;

    if (active) {
        const int i = si;
        if (tid < 32) {
            const int kk = tid >> 2;
            const int c  = tid & 3;
            const float v0 = vectors[2 * kk + 0];
            const float v1 = vectors[2 * kk + 1];
            const float fx = floorf(v0);
            const float fy = floorf(v1);
            const int   sx = (int)fx;
            const int   sy = (int)fy;
            const float px = fx - v0;
            const float py = fy - v1;
            const int dx = c >> 1;       // corner order matches reference
            const int dy = c & 1;
            const float wx = dx ? (1.0f - px) : px;
            const float wy = dy ? (1.0f - py) : py;
            int t1 = i - (sy + dy);
            t1 = min(max(t1, 0), CLIPM);
            int r = t1 - (sx + dx);
            r = min(max(r, 0), CLIPM);
            const int   base = (kk * NR + r) * IMG_W;
            const float w    = wx * wy;

            // Merge taps with identical gather row: sum their weights.
            const unsigned mask   = __match_any_sync(0xffffffffu, base);
            const int      leader = __ffs(mask) - 1;
            float tot = 0.0f;
            #pragma unroll
            for (int l = 0; l < 32; l++) {
                const float wl = __shfl_sync(0xffffffffu, w, l);
                if (mask & (1u << l)) tot += wl;
            }
            const unsigned lmask = __ballot_sync(0xffffffffu, tid == leader);
            if (tid == leader) {
                const int pos = __popc(lmask & ((1u << tid) - 1u));
                sbase[pos] = base;
                sw[pos]    = tot;
            }
            if (tid == 0) sntap = __popc(lmask);
        }
        __syncthreads();

        const int ntap = sntap;
        const int joff = half * (IMG_W / 2) + 2 * tid;   // float2 column
        float2 acc = make_float2(0.f, 0.f);
        #pragma unroll 4
        for (int t = 0; t < ntap; t++) {
            const float  wv = sw[t];
            const float2 v  = *(const float2*)&g_F[sbase[t] + joff];
            acc.x = fmaf(wv, v.x, acc.x);
            acc.y = fmaf(wv, v.y, acc.y);
        }
        m = fmaxf(acc.x, acc.y);

        #pragma unroll
        for (int o = 16; o > 0; o >>= 1)
            m = fmaxf(m, __shfl_xor_sync(0xffffffffu, m, o));
        if ((tid & 31) == 0) smax[tid >> 5] = m;
        __syncthreads();
        if (tid == 0) {
            #pragma unroll
            for (int w = 1; w < 12; w++) m = fmaxf(m, smax[w]);
        }
    }

    if (tid == 0) {
        if (active) atomicMax(&g_enc, enc_f(m));
        __threadfence();
        const unsigned old = atomicAdd(&g_done, 1u);
        if (old == (unsigned)(NBLK3 - 1)) {
            const unsigned u = atomicOr(&g_enc, 0u);   // coherent read
            out[0] = dec_f(u) * (1.0f / 7.0f);
        }
    }
}

extern "C" void kernel_launch(void* const* d_in, const int* in_sizes, int n_in,
                              void* d_out, int out_size) {
    const float* x        = (const float*)d_in[0];
    const float* patterns = (const float*)d_in[1];
    const float* vectors  = (const float*)d_in[2];
    float* out = (float*)d_out;

    geneo1_kernel<<<NBLK1 + 1, BS1>>>(x, patterns, vectors);
    geneo3_kernel<<<NBLK3, 384>>>(vectors, out);
}